// round 5
// baseline (speedup 1.0000x reference)
#include <cuda_runtime.h>
#include <cuda_bf16.h>
#include <cstdint>

#define NB 32
#define L  2048
#define D  64
#define BM 64
#define BN 64

// scratch: per-row running max and sum + mask-dtype flag (__device__ globals allowed)
__device__ float g_m[NB * L];
__device__ float g_l[NB * L];
__device__ int   g_mflag;   // 1 = mask is int32, 0 = mask is uint8

__device__ __forceinline__ uint32_t pack2(__nv_bfloat16 a, __nv_bfloat16 b) {
    return (uint32_t)__bfloat16_as_ushort(a) | ((uint32_t)__bfloat16_as_ushort(b) << 16);
}

// split fp32 pair into bf16 hi pair + bf16 lo (residual) pair
__device__ __forceinline__ void split2(float x, float y, uint32_t& hi, uint32_t& lo) {
    __nv_bfloat16 hx = __float2bfloat16(x);
    __nv_bfloat16 hy = __float2bfloat16(y);
    float rx = x - __bfloat162float(hx);
    float ry = y - __bfloat162float(hy);
    hi = pack2(hx, hy);
    lo = pack2(__float2bfloat16(rx), __float2bfloat16(ry));
}

__device__ __forceinline__ void mma_bf16(float c[4], const uint32_t a[4], uint32_t b0, uint32_t b1) {
    asm volatile(
        "mma.sync.aligned.m16n8k16.row.col.f32.bf16.bf16.f32 "
        "{%0,%1,%2,%3}, {%4,%5,%6,%7}, {%8,%9}, {%0,%1,%2,%3};\n"
        : "+f"(c[0]), "+f"(c[1]), "+f"(c[2]), "+f"(c[3])
        : "r"(a[0]), "r"(a[1]), "r"(a[2]), "r"(a[3]), "r"(b0), "r"(b1));
}

// Detect mask dtype: int32 {0,1} values have zero bytes at offsets %4 != 0.
__global__ void probe_mask(const uint8_t* __restrict__ bm) {
    __shared__ int cnt;
    if (threadIdx.x == 0) cnt = 0;
    __syncthreads();
    int c = 0;
    for (int i = threadIdx.x; i < 4096; i += blockDim.x)
        if ((i & 3) != 0 && bm[i] != 0) c++;
    atomicAdd(&cnt, c);
    __syncthreads();
    if (threadIdx.x == 0) g_mflag = (cnt == 0) ? 1 : 0;
}

__global__ void __launch_bounds__(128)
attn_flash(const float* __restrict__ q, const float* __restrict__ k,
           const float* __restrict__ v, const int* __restrict__ dmask,
           const uint8_t* __restrict__ bmask,
           float* __restrict__ out, float* __restrict__ attn)
{
    // padded to 72 elems/row (144B) -> conflict-free fragment loads
    __shared__ __nv_bfloat16 sKhi[BN][72];
    __shared__ __nv_bfloat16 sKlo[BN][72];
    __shared__ __nv_bfloat16 sVhi[D][72];   // transposed: [d][n]
    __shared__ __nv_bfloat16 sVlo[D][72];

    const int b    = blockIdx.y;
    const int q0   = blockIdx.x * BM;
    const int tid  = threadIdx.x;
    const int warp = tid >> 5;
    const int lane = tid & 31;
    const int g    = lane >> 2;
    const int quad = lane & 3;
    const int row0 = q0 + warp * 16 + g;   // global q row for c0/c1
    const int row1 = row0 + 8;             // for c2/c3

    const bool mi32 = (g_mflag != 0);      // hoisted to a register

    // ---- load Q A-fragments once (hi/lo split), 4 k16-steps over D=64 ----
    uint32_t aQh[16], aQl[16];
    {
        const float* qb = q + ((size_t)b * L) * D;
        #pragma unroll
        for (int ks = 0; ks < 4; ks++) {
            int c0 = ks * 16 + quad * 2;
            float2 x0 = *reinterpret_cast<const float2*>(qb + (size_t)row0 * D + c0);
            float2 x1 = *reinterpret_cast<const float2*>(qb + (size_t)row1 * D + c0);
            float2 x2 = *reinterpret_cast<const float2*>(qb + (size_t)row0 * D + c0 + 8);
            float2 x3 = *reinterpret_cast<const float2*>(qb + (size_t)row1 * D + c0 + 8);
            split2(x0.x, x0.y, aQh[ks*4+0], aQl[ks*4+0]);
            split2(x1.x, x1.y, aQh[ks*4+1], aQl[ks*4+1]);
            split2(x2.x, x2.y, aQh[ks*4+2], aQl[ks*4+2]);
            split2(x3.x, x3.y, aQh[ks*4+3], aQl[ks*4+3]);
        }
    }

    float oAcc[8][4];
    #pragma unroll
    for (int i = 0; i < 8; i++)
        oAcc[i][0] = oAcc[i][1] = oAcc[i][2] = oAcc[i][3] = 0.f;
    float mrun0 = -INFINITY, mrun1 = -INFINITY;
    float lrun0 = 0.f, lrun1 = 0.f;

    const float*   kb    = k     + ((size_t)b * L) * D;
    const float*   vb    = v     + ((size_t)b * L) * D;
    const int*     dmb   = dmask + (size_t)b * L * L;
    const uint8_t* bmb_u = bmask + (size_t)b * L * L;
    const int*     bmb_i = reinterpret_cast<const int*>(bmask) + (size_t)b * L * L;
    float*         attnb = attn  + (size_t)b * L * L;

    for (int j = 0; j < L / BN; j++) {
        // ---- stage K (row-major) and V (transposed) as split bf16 ----
        {
            const float* kt = kb + (size_t)j * BN * D;
            const float* vt = vb + (size_t)j * BN * D;
            #pragma unroll
            for (int t = 0; t < 8; t++) {
                int idx = t * 128 + tid;        // float4 index, 1024 total
                int r = idx >> 4;
                int c = (idx & 15) << 2;
                float4 k4 = *reinterpret_cast<const float4*>(kt + (size_t)r * D + c);
                float4 v4 = *reinterpret_cast<const float4*>(vt + (size_t)r * D + c);
                __nv_bfloat16 h;
                h = __float2bfloat16(k4.x); sKhi[r][c+0] = h; sKlo[r][c+0] = __float2bfloat16(k4.x - __bfloat162float(h));
                h = __float2bfloat16(k4.y); sKhi[r][c+1] = h; sKlo[r][c+1] = __float2bfloat16(k4.y - __bfloat162float(h));
                h = __float2bfloat16(k4.z); sKhi[r][c+2] = h; sKlo[r][c+2] = __float2bfloat16(k4.z - __bfloat162float(h));
                h = __float2bfloat16(k4.w); sKhi[r][c+3] = h; sKlo[r][c+3] = __float2bfloat16(k4.w - __bfloat162float(h));
                h = __float2bfloat16(v4.x); sVhi[c+0][r] = h; sVlo[c+0][r] = __float2bfloat16(v4.x - __bfloat162float(h));
                h = __float2bfloat16(v4.y); sVhi[c+1][r] = h; sVlo[c+1][r] = __float2bfloat16(v4.y - __bfloat162float(h));
                h = __float2bfloat16(v4.z); sVhi[c+2][r] = h; sVlo[c+2][r] = __float2bfloat16(v4.z - __bfloat162float(h));
                h = __float2bfloat16(v4.w); sVhi[c+3][r] = h; sVlo[c+3][r] = __float2bfloat16(v4.w - __bfloat162float(h));
            }
        }
        __syncthreads();

        // ---- S = Q K^T (split bf16: hi*hi + hi*lo + lo*hi) ----
        float sAcc[8][4];
        #pragma unroll
        for (int nt = 0; nt < 8; nt++)
            sAcc[nt][0] = sAcc[nt][1] = sAcc[nt][2] = sAcc[nt][3] = 0.f;

        #pragma unroll
        for (int nt = 0; nt < 8; nt++) {
            int n = nt * 8 + g;
            #pragma unroll
            for (int ks = 0; ks < 4; ks++) {
                int d0 = ks * 16 + quad * 2;
                uint32_t bh0 = *reinterpret_cast<const uint32_t*>(&sKhi[n][d0]);
                uint32_t bh1 = *reinterpret_cast<const uint32_t*>(&sKhi[n][d0 + 8]);
                uint32_t bl0 = *reinterpret_cast<const uint32_t*>(&sKlo[n][d0]);
                uint32_t bl1 = *reinterpret_cast<const uint32_t*>(&sKlo[n][d0 + 8]);
                mma_bf16(sAcc[nt], &aQh[ks*4], bh0, bh1);
                mma_bf16(sAcc[nt], &aQh[ks*4], bl0, bl1);
                mma_bf16(sAcc[nt], &aQl[ks*4], bh0, bh1);
            }
        }

        // ---- scale, masks, write raw masked scores, tile row-max ----
        float tmax0 = -INFINITY, tmax1 = -INFINITY;
        #pragma unroll
        for (int nt = 0; nt < 8; nt++) {
            int col = j * BN + nt * 8 + quad * 2;
            int2 d0v = *reinterpret_cast<const int2*>(dmb + (size_t)row0 * L + col);
            int2 d1v = *reinterpret_cast<const int2*>(dmb + (size_t)row1 * L + col);
            bool mk0x, mk0y, mk1x, mk1y;
            if (mi32) {
                int2 a0 = *reinterpret_cast<const int2*>(bmb_i + (size_t)row0 * L + col);
                int2 a1 = *reinterpret_cast<const int2*>(bmb_i + (size_t)row1 * L + col);
                mk0x = (a0.x != 0); mk0y = (a0.y != 0);
                mk1x = (a1.x != 0); mk1y = (a1.y != 0);
            } else {
                uchar2 a0 = *reinterpret_cast<const uchar2*>(bmb_u + (size_t)row0 * L + col);
                uchar2 a1 = *reinterpret_cast<const uchar2*>(bmb_u + (size_t)row1 * L + col);
                mk0x = (a0.x != 0); mk0y = (a0.y != 0);
                mk1x = (a1.x != 0); mk1y = (a1.y != 0);
            }
            float s0 = sAcc[nt][0] * 0.125f;
            float s1 = sAcc[nt][1] * 0.125f;
            float s2 = sAcc[nt][2] * 0.125f;
            float s3 = sAcc[nt][3] * 0.125f;
            if (mk0x)       s0 = -INFINITY;
            if (d0v.x == 0) s0 = -1e32f;
            if (mk0y)       s1 = -INFINITY;
            if (d0v.y == 0) s1 = -1e32f;
            if (mk1x)       s2 = -INFINITY;
            if (d1v.x == 0) s2 = -1e32f;
            if (mk1y)       s3 = -INFINITY;
            if (d1v.y == 0) s3 = -1e32f;
            *reinterpret_cast<float2*>(attnb + (size_t)row0 * L + col) = make_float2(s0, s1);
            *reinterpret_cast<float2*>(attnb + (size_t)row1 * L + col) = make_float2(s2, s3);
            sAcc[nt][0] = s0; sAcc[nt][1] = s1; sAcc[nt][2] = s2; sAcc[nt][3] = s3;
            tmax0 = fmaxf(tmax0, fmaxf(s0, s1));
            tmax1 = fmaxf(tmax1, fmaxf(s2, s3));
        }
        tmax0 = fmaxf(tmax0, __shfl_xor_sync(0xffffffffu, tmax0, 1));
        tmax0 = fmaxf(tmax0, __shfl_xor_sync(0xffffffffu, tmax0, 2));
        tmax1 = fmaxf(tmax1, __shfl_xor_sync(0xffffffffu, tmax1, 1));
        tmax1 = fmaxf(tmax1, __shfl_xor_sync(0xffffffffu, tmax1, 2));

        float mnew0 = fmaxf(mrun0, tmax0);
        float mnew1 = fmaxf(mrun1, tmax1);
        float alpha0 = (mnew0 == -INFINITY) ? 1.0f : __expf(mrun0 - mnew0);
        float alpha1 = (mnew1 == -INFINITY) ? 1.0f : __expf(mrun1 - mnew1);
        mrun0 = mnew0; mrun1 = mnew1;

        // ---- p = exp(s - m), row sums ----
        float rs0 = 0.f, rs1 = 0.f;
        #pragma unroll
        for (int nt = 0; nt < 8; nt++) {
            float p0 = (sAcc[nt][0] <= -1e30f) ? 0.f : __expf(sAcc[nt][0] - mnew0);
            float p1 = (sAcc[nt][1] <= -1e30f) ? 0.f : __expf(sAcc[nt][1] - mnew0);
            float p2 = (sAcc[nt][2] <= -1e30f) ? 0.f : __expf(sAcc[nt][2] - mnew1);
            float p3 = (sAcc[nt][3] <= -1e30f) ? 0.f : __expf(sAcc[nt][3] - mnew1);
            sAcc[nt][0] = p0; sAcc[nt][1] = p1; sAcc[nt][2] = p2; sAcc[nt][3] = p3;
            rs0 += p0 + p1;
            rs1 += p2 + p3;
        }
        rs0 += __shfl_xor_sync(0xffffffffu, rs0, 1);
        rs0 += __shfl_xor_sync(0xffffffffu, rs0, 2);
        rs1 += __shfl_xor_sync(0xffffffffu, rs1, 1);
        rs1 += __shfl_xor_sync(0xffffffffu, rs1, 2);
        lrun0 = lrun0 * alpha0 + rs0;
        lrun1 = lrun1 * alpha1 + rs1;

        // ---- O = O*alpha + P @ V (split bf16) ----
        #pragma unroll
        for (int dt = 0; dt < 8; dt++) {
            oAcc[dt][0] *= alpha0; oAcc[dt][1] *= alpha0;
            oAcc[dt][2] *= alpha1; oAcc[dt][3] *= alpha1;
        }
        #pragma unroll
        for (int kn = 0; kn < 4; kn++) {
            // S C-fragment layout == P A-fragment layout
            uint32_t pah[4], pal[4];
            split2(sAcc[2*kn  ][0], sAcc[2*kn  ][1], pah[0], pal[0]);
            split2(sAcc[2*kn  ][2], sAcc[2*kn  ][3], pah[1], pal[1]);
            split2(sAcc[2*kn+1][0], sAcc[2*kn+1][1], pah[2], pal[2]);
            split2(sAcc[2*kn+1][2], sAcc[2*kn+1][3], pah[3], pal[3]);
            int n0 = kn * 16 + quad * 2;
            #pragma unroll
            for (int dt = 0; dt < 8; dt++) {
                int dcol = dt * 8 + g;
                uint32_t bh0 = *reinterpret_cast<const uint32_t*>(&sVhi[dcol][n0]);
                uint32_t bh1 = *reinterpret_cast<const uint32_t*>(&sVhi[dcol][n0 + 8]);
                uint32_t bl0 = *reinterpret_cast<const uint32_t*>(&sVlo[dcol][n0]);
                uint32_t bl1 = *reinterpret_cast<const uint32_t*>(&sVlo[dcol][n0 + 8]);
                mma_bf16(oAcc[dt], pah, bh0, bh1);
                mma_bf16(oAcc[dt], pah, bl0, bl1);
                mma_bf16(oAcc[dt], pal, bh0, bh1);
            }
        }
        __syncthreads();
    }

    // ---- epilogue: O / l, store stats ----
    float rl0 = 1.0f / lrun0;
    float rl1 = 1.0f / lrun1;
    float* ob = out + ((size_t)b * L) * D;
    #pragma unroll
    for (int dt = 0; dt < 8; dt++) {
        int dc = dt * 8 + quad * 2;
        *reinterpret_cast<float2*>(ob + (size_t)row0 * D + dc) =
            make_float2(oAcc[dt][0] * rl0, oAcc[dt][1] * rl0);
        *reinterpret_cast<float2*>(ob + (size_t)row1 * D + dc) =
            make_float2(oAcc[dt][2] * rl1, oAcc[dt][3] * rl1);
    }
    if (quad == 0) {
        g_m[(size_t)b * L + row0] = mrun0;
        g_m[(size_t)b * L + row1] = mrun1;
        g_l[(size_t)b * L + row0] = lrun0;
        g_l[(size_t)b * L + row1] = lrun1;
    }
}

__global__ void normalize_attn(float* __restrict__ attn)
{
    const size_t total4 = (size_t)NB * L * L / 4;
    for (size_t i = (size_t)blockIdx.x * blockDim.x + threadIdx.x; i < total4;
         i += (size_t)gridDim.x * blockDim.x) {
        size_t row = i >> 9;               // 512 float4 per attn row
        float m  = g_m[row];
        float rl = 1.0f / g_l[row];
        float4 s = reinterpret_cast<float4*>(attn)[i];
        s.x = __expf(s.x - m) * rl;        // -inf / -1e32 -> exactly 0
        s.y = __expf(s.y - m) * rl;
        s.z = __expf(s.z - m) * rl;
        s.w = __expf(s.w - m) * rl;
        reinterpret_cast<float4*>(attn)[i] = s;
    }
}

extern "C" void kernel_launch(void* const* d_in, const int* in_sizes, int n_in,
                              void* d_out, int out_size)
{
    // Robust binding: identify inputs by element count (host-readable).
    // q,k,v have NB*L*D elements; diag_mask & mask have NB*L*L. Relative order
    // within each size group is preserved (q,k,v) and (diag_mask, mask).
    const int SMALL = NB * L * D;       // 4194304
    const void* small_p[3] = {nullptr, nullptr, nullptr};
    const void* big_p[2]   = {nullptr, nullptr};
    int ns = 0, nb = 0;
    for (int i = 0; i < n_in; i++) {
        if (in_sizes[i] == SMALL) { if (ns < 3) small_p[ns++] = d_in[i]; }
        else                      { if (nb < 2) big_p[nb++]   = d_in[i]; }
    }
    const float*   q, *k, *v;
    const int*     dm;
    const uint8_t* bm;
    if (ns == 3 && nb == 2) {
        q  = (const float*)small_p[0];
        k  = (const float*)small_p[1];
        v  = (const float*)small_p[2];
        dm = (const int*)big_p[0];
        bm = (const uint8_t*)big_p[1];
    } else {  // fallback: positional (dict order)
        q  = (const float*)d_in[0];
        k  = (const float*)d_in[1];
        v  = (const float*)d_in[2];
        dm = (const int*)d_in[3];
        bm = (const uint8_t*)d_in[4];
    }

    float* out  = (float*)d_out;                      // [B, L, D] first
    float* attn = out + (size_t)NB * L * D;           // then [B, L, L]

    probe_mask<<<1, 256>>>(bm);
    dim3 grid(L / BM, NB);
    attn_flash<<<grid, 128>>>(q, k, v, dm, bm, out, attn);
    normalize_attn<<<4096, 256>>>(attn);
}

// round 6
// speedup vs baseline: 1.1583x; 1.1583x over previous
#include <cuda_runtime.h>
#include <cuda_bf16.h>
#include <cstdint>

#define NB 32
#define L  2048
#define D  64
#define BM 64
#define BN 64

__device__ __forceinline__ uint32_t pack2(__nv_bfloat16 a, __nv_bfloat16 b) {
    return (uint32_t)__bfloat16_as_ushort(a) | ((uint32_t)__bfloat16_as_ushort(b) << 16);
}

// split fp32 pair into bf16 hi pair + bf16 lo (residual) pair
__device__ __forceinline__ void split2(float x, float y, uint32_t& hi, uint32_t& lo) {
    __nv_bfloat16 hx = __float2bfloat16(x);
    __nv_bfloat16 hy = __float2bfloat16(y);
    float rx = x - __bfloat162float(hx);
    float ry = y - __bfloat162float(hy);
    hi = pack2(hx, hy);
    lo = pack2(__float2bfloat16(rx), __float2bfloat16(ry));
}

__device__ __forceinline__ void mma_bf16(float c[4], const uint32_t a[4], uint32_t b0, uint32_t b1) {
    asm volatile(
        "mma.sync.aligned.m16n8k16.row.col.f32.bf16.bf16.f32 "
        "{%0,%1,%2,%3}, {%4,%5,%6,%7}, {%8,%9}, {%0,%1,%2,%3};\n"
        : "+f"(c[0]), "+f"(c[1]), "+f"(c[2]), "+f"(c[3])
        : "r"(a[0]), "r"(a[1]), "r"(a[2]), "r"(a[3]), "r"(b0), "r"(b1));
}

__global__ void __launch_bounds__(128)
attn_fused(const float* __restrict__ q, const float* __restrict__ k,
           const float* __restrict__ v, const int* __restrict__ dmask,
           const uint8_t* __restrict__ bmask,
           float* __restrict__ out, float* __restrict__ attn)
{
    // padded to 72 elems/row (144B) -> conflict-free fragment loads
    __shared__ __nv_bfloat16 sKhi[BN][72];
    __shared__ __nv_bfloat16 sKlo[BN][72];
    __shared__ __nv_bfloat16 sVhi[D][72];   // transposed: [d][n]
    __shared__ __nv_bfloat16 sVlo[D][72];
    __shared__ float sMj[32][64];           // per-tile running max, later cf
    __shared__ float sStatM[64];
    __shared__ float sStatL[64];

    const int b    = blockIdx.y;
    const int q0   = blockIdx.x * BM;
    const int tid  = threadIdx.x;
    const int warp = tid >> 5;
    const int lane = tid & 31;
    const int g    = lane >> 2;
    const int quad = lane & 3;
    const int rl0  = warp * 16 + g;        // local row for c0/c1
    const int rl1  = rl0 + 8;              // local row for c2/c3
    const int row0 = q0 + rl0;             // global q row
    const int row1 = q0 + rl1;

    const float*   kb    = k     + ((size_t)b * L) * D;
    const float*   vb    = v     + ((size_t)b * L) * D;
    const int*     dmb   = dmask + (size_t)b * L * L;
    const uint8_t* bmb_u = bmask + (size_t)b * L * L;
    const int*     bmb_i = reinterpret_cast<const int*>(bmask) + (size_t)b * L * L;
    float*         attnb = attn  + (size_t)b * L * L;

    // ---- inline mask-dtype probe: int32 {0,1} has zero bytes at offset%4!=0 ----
    int nz = 0;
    {
        const uint4* p4 = reinterpret_cast<const uint4*>(bmb_u);
        uint4 w0 = p4[tid];
        uint4 w1 = p4[128 + tid];
        nz = (int)((w0.x | w0.y | w0.z | w0.w | w1.x | w1.y | w1.z | w1.w) & 0xFFFFFF00u);
    }
    const bool mi32 = (__syncthreads_or(nz) == 0);

    // ---- load Q A-fragments once (hi/lo split), temperature folded in (x2^-3 exact) ----
    uint32_t aQh[16], aQl[16];
    {
        const float* qb = q + ((size_t)b * L) * D;
        #pragma unroll
        for (int ks = 0; ks < 4; ks++) {
            int c0 = ks * 16 + quad * 2;
            float2 x0 = *reinterpret_cast<const float2*>(qb + (size_t)row0 * D + c0);
            float2 x1 = *reinterpret_cast<const float2*>(qb + (size_t)row1 * D + c0);
            float2 x2 = *reinterpret_cast<const float2*>(qb + (size_t)row0 * D + c0 + 8);
            float2 x3 = *reinterpret_cast<const float2*>(qb + (size_t)row1 * D + c0 + 8);
            split2(x0.x * 0.125f, x0.y * 0.125f, aQh[ks*4+0], aQl[ks*4+0]);
            split2(x1.x * 0.125f, x1.y * 0.125f, aQh[ks*4+1], aQl[ks*4+1]);
            split2(x2.x * 0.125f, x2.y * 0.125f, aQh[ks*4+2], aQl[ks*4+2]);
            split2(x3.x * 0.125f, x3.y * 0.125f, aQh[ks*4+3], aQl[ks*4+3]);
        }
    }

    float oAcc[8][4];
    #pragma unroll
    for (int i = 0; i < 8; i++)
        oAcc[i][0] = oAcc[i][1] = oAcc[i][2] = oAcc[i][3] = 0.f;
    float mrun0 = -INFINITY, mrun1 = -INFINITY;
    float lrun0 = 0.f, lrun1 = 0.f;

    for (int j = 0; j < L / BN; j++) {
        // ---- stage K (row-major) and V (transposed) as split bf16 ----
        {
            const float* kt = kb + (size_t)j * BN * D;
            const float* vt = vb + (size_t)j * BN * D;
            #pragma unroll
            for (int t = 0; t < 8; t++) {
                int idx = t * 128 + tid;        // float4 index, 1024 total
                int r = idx >> 4;
                int c = (idx & 15) << 2;
                float4 k4 = *reinterpret_cast<const float4*>(kt + (size_t)r * D + c);
                float4 v4 = *reinterpret_cast<const float4*>(vt + (size_t)r * D + c);
                __nv_bfloat16 h;
                h = __float2bfloat16(k4.x); sKhi[r][c+0] = h; sKlo[r][c+0] = __float2bfloat16(k4.x - __bfloat162float(h));
                h = __float2bfloat16(k4.y); sKhi[r][c+1] = h; sKlo[r][c+1] = __float2bfloat16(k4.y - __bfloat162float(h));
                h = __float2bfloat16(k4.z); sKhi[r][c+2] = h; sKlo[r][c+2] = __float2bfloat16(k4.z - __bfloat162float(h));
                h = __float2bfloat16(k4.w); sKhi[r][c+3] = h; sKlo[r][c+3] = __float2bfloat16(k4.w - __bfloat162float(h));
                h = __float2bfloat16(v4.x); sVhi[c+0][r] = h; sVlo[c+0][r] = __float2bfloat16(v4.x - __bfloat162float(h));
                h = __float2bfloat16(v4.y); sVhi[c+1][r] = h; sVlo[c+1][r] = __float2bfloat16(v4.y - __bfloat162float(h));
                h = __float2bfloat16(v4.z); sVhi[c+2][r] = h; sVlo[c+2][r] = __float2bfloat16(v4.z - __bfloat162float(h));
                h = __float2bfloat16(v4.w); sVhi[c+3][r] = h; sVlo[c+3][r] = __float2bfloat16(v4.w - __bfloat162float(h));
            }
        }
        __syncthreads();

        // ---- S = Q K^T (split bf16: hi*hi + hi*lo + lo*hi) ----
        float sAcc[8][4];
        #pragma unroll
        for (int nt = 0; nt < 8; nt++)
            sAcc[nt][0] = sAcc[nt][1] = sAcc[nt][2] = sAcc[nt][3] = 0.f;

        #pragma unroll
        for (int nt = 0; nt < 8; nt++) {
            int n = nt * 8 + g;
            #pragma unroll
            for (int ks = 0; ks < 4; ks++) {
                int d0 = ks * 16 + quad * 2;
                uint32_t bh0 = *reinterpret_cast<const uint32_t*>(&sKhi[n][d0]);
                uint32_t bh1 = *reinterpret_cast<const uint32_t*>(&sKhi[n][d0 + 8]);
                uint32_t bl0 = *reinterpret_cast<const uint32_t*>(&sKlo[n][d0]);
                uint32_t bl1 = *reinterpret_cast<const uint32_t*>(&sKlo[n][d0 + 8]);
                mma_bf16(sAcc[nt], &aQh[ks*4], bh0, bh1);
                mma_bf16(sAcc[nt], &aQh[ks*4], bl0, bl1);
                mma_bf16(sAcc[nt], &aQl[ks*4], bh0, bh1);
            }
        }

        // ---- masks, tile row-max ----
        float tmax0 = -INFINITY, tmax1 = -INFINITY;
        #pragma unroll
        for (int nt = 0; nt < 8; nt++) {
            int col = j * BN + nt * 8 + quad * 2;
            int2 d0v = *reinterpret_cast<const int2*>(dmb + (size_t)row0 * L + col);
            int2 d1v = *reinterpret_cast<const int2*>(dmb + (size_t)row1 * L + col);
            bool mk0x, mk0y, mk1x, mk1y;
            if (mi32) {
                int2 a0 = *reinterpret_cast<const int2*>(bmb_i + (size_t)row0 * L + col);
                int2 a1 = *reinterpret_cast<const int2*>(bmb_i + (size_t)row1 * L + col);
                mk0x = (a0.x != 0); mk0y = (a0.y != 0);
                mk1x = (a1.x != 0); mk1y = (a1.y != 0);
            } else {
                uchar2 a0 = *reinterpret_cast<const uchar2*>(bmb_u + (size_t)row0 * L + col);
                uchar2 a1 = *reinterpret_cast<const uchar2*>(bmb_u + (size_t)row1 * L + col);
                mk0x = (a0.x != 0); mk0y = (a0.y != 0);
                mk1x = (a1.x != 0); mk1y = (a1.y != 0);
            }
            float s0 = sAcc[nt][0];
            float s1 = sAcc[nt][1];
            float s2 = sAcc[nt][2];
            float s3 = sAcc[nt][3];
            if (mk0x)       s0 = -INFINITY;
            if (d0v.x == 0) s0 = -1e32f;
            if (mk0y)       s1 = -INFINITY;
            if (d0v.y == 0) s1 = -1e32f;
            if (mk1x)       s2 = -INFINITY;
            if (d1v.x == 0) s2 = -1e32f;
            if (mk1y)       s3 = -INFINITY;
            if (d1v.y == 0) s3 = -1e32f;
            sAcc[nt][0] = s0; sAcc[nt][1] = s1; sAcc[nt][2] = s2; sAcc[nt][3] = s3;
            tmax0 = fmaxf(tmax0, fmaxf(s0, s1));
            tmax1 = fmaxf(tmax1, fmaxf(s2, s3));
        }
        tmax0 = fmaxf(tmax0, __shfl_xor_sync(0xffffffffu, tmax0, 1));
        tmax0 = fmaxf(tmax0, __shfl_xor_sync(0xffffffffu, tmax0, 2));
        tmax1 = fmaxf(tmax1, __shfl_xor_sync(0xffffffffu, tmax1, 1));
        tmax1 = fmaxf(tmax1, __shfl_xor_sync(0xffffffffu, tmax1, 2));

        float mnew0 = fmaxf(mrun0, tmax0);
        float mnew1 = fmaxf(mrun1, tmax1);
        float alpha0 = (mnew0 == -INFINITY) ? 1.0f : __expf(mrun0 - mnew0);
        float alpha1 = (mnew1 == -INFINITY) ? 1.0f : __expf(mrun1 - mnew1);
        mrun0 = mnew0; mrun1 = mnew1;

        // record this tile's max for the epilogue correction factor
        if (quad == 0) {
            sMj[j][rl0] = mnew0;
            sMj[j][rl1] = mnew1;
        }

        // ---- p = exp(s - m_j): store p to attn (raw, corrected in epilogue), row sums ----
        float rs0 = 0.f, rs1 = 0.f;
        #pragma unroll
        for (int nt = 0; nt < 8; nt++) {
            float p0 = __expf(sAcc[nt][0] - mnew0);   // -inf/-1e32 underflow to exact 0
            float p1 = __expf(sAcc[nt][1] - mnew0);
            float p2 = __expf(sAcc[nt][2] - mnew1);
            float p3 = __expf(sAcc[nt][3] - mnew1);
            int col = j * BN + nt * 8 + quad * 2;
            *reinterpret_cast<float2*>(attnb + (size_t)row0 * L + col) = make_float2(p0, p1);
            *reinterpret_cast<float2*>(attnb + (size_t)row1 * L + col) = make_float2(p2, p3);
            sAcc[nt][0] = p0; sAcc[nt][1] = p1; sAcc[nt][2] = p2; sAcc[nt][3] = p3;
            rs0 += p0 + p1;
            rs1 += p2 + p3;
        }
        rs0 += __shfl_xor_sync(0xffffffffu, rs0, 1);
        rs0 += __shfl_xor_sync(0xffffffffu, rs0, 2);
        rs1 += __shfl_xor_sync(0xffffffffu, rs1, 1);
        rs1 += __shfl_xor_sync(0xffffffffu, rs1, 2);
        lrun0 = lrun0 * alpha0 + rs0;
        lrun1 = lrun1 * alpha1 + rs1;

        // ---- O = O*alpha + P @ V (split bf16) ----
        #pragma unroll
        for (int dt = 0; dt < 8; dt++) {
            oAcc[dt][0] *= alpha0; oAcc[dt][1] *= alpha0;
            oAcc[dt][2] *= alpha1; oAcc[dt][3] *= alpha1;
        }
        #pragma unroll
        for (int kn = 0; kn < 4; kn++) {
            // S C-fragment layout == P A-fragment layout
            uint32_t pah[4], pal[4];
            split2(sAcc[2*kn  ][0], sAcc[2*kn  ][1], pah[0], pal[0]);
            split2(sAcc[2*kn  ][2], sAcc[2*kn  ][3], pah[1], pal[1]);
            split2(sAcc[2*kn+1][0], sAcc[2*kn+1][1], pah[2], pal[2]);
            split2(sAcc[2*kn+1][2], sAcc[2*kn+1][3], pah[3], pal[3]);
            int n0 = kn * 16 + quad * 2;
            #pragma unroll
            for (int dt = 0; dt < 8; dt++) {
                int dcol = dt * 8 + g;
                uint32_t bh0 = *reinterpret_cast<const uint32_t*>(&sVhi[dcol][n0]);
                uint32_t bh1 = *reinterpret_cast<const uint32_t*>(&sVhi[dcol][n0 + 8]);
                uint32_t bl0 = *reinterpret_cast<const uint32_t*>(&sVlo[dcol][n0]);
                uint32_t bl1 = *reinterpret_cast<const uint32_t*>(&sVlo[dcol][n0 + 8]);
                mma_bf16(oAcc[dt], pah, bh0, bh1);
                mma_bf16(oAcc[dt], pah, bl0, bl1);
                mma_bf16(oAcc[dt], pal, bh0, bh1);
            }
        }
        __syncthreads();
    }

    // ---- O epilogue: O / l ----
    float rlv0 = 1.0f / lrun0;
    float rlv1 = 1.0f / lrun1;
    float* ob = out + ((size_t)b * L) * D;
    #pragma unroll
    for (int dt = 0; dt < 8; dt++) {
        int dc = dt * 8 + quad * 2;
        *reinterpret_cast<float2*>(ob + (size_t)row0 * D + dc) =
            make_float2(oAcc[dt][0] * rlv0, oAcc[dt][1] * rlv0);
        *reinterpret_cast<float2*>(ob + (size_t)row1 * D + dc) =
            make_float2(oAcc[dt][2] * rlv1, oAcc[dt][3] * rlv1);
    }

    // ---- attn epilogue: per-(row,tile) correction cf = exp(m_j - m_fin) / l ----
    if (quad == 0) {
        sStatM[rl0] = mrun0; sStatM[rl1] = mrun1;
        sStatL[rl0] = rlv0;  sStatL[rl1] = rlv1;
    }
    __syncthreads();
    #pragma unroll
    for (int i = tid; i < 32 * 64; i += 128) {
        int t = i >> 6, r = i & 63;
        sMj[t][r] = __expf(sMj[t][r] - sStatM[r]) * sStatL[r];
    }
    __syncthreads();

    // stream 64 rows x 512 float4: p *= cf  (intra-block gmem visibility via __syncthreads)
    float4* a4 = reinterpret_cast<float4*>(attnb + (size_t)q0 * L);
    #pragma unroll 4
    for (int i = tid; i < 64 * 512; i += 128) {
        int r  = i >> 9;
        int c4 = i & 511;
        float cf = sMj[c4 >> 4][r];
        float4 sv = a4[i];
        sv.x *= cf; sv.y *= cf; sv.z *= cf; sv.w *= cf;
        a4[i] = sv;
    }
}

extern "C" void kernel_launch(void* const* d_in, const int* in_sizes, int n_in,
                              void* d_out, int out_size)
{
    // Robust binding by element count: q,k,v = NB*L*D; diag_mask, mask = NB*L*L.
    const int SMALL = NB * L * D;       // 4194304
    const void* small_p[3] = {nullptr, nullptr, nullptr};
    const void* big_p[2]   = {nullptr, nullptr};
    int ns = 0, nb = 0;
    for (int i = 0; i < n_in; i++) {
        if (in_sizes[i] == SMALL) { if (ns < 3) small_p[ns++] = d_in[i]; }
        else                      { if (nb < 2) big_p[nb++]   = d_in[i]; }
    }
    const float*   q, *k, *v;
    const int*     dm;
    const uint8_t* bm;
    if (ns == 3 && nb == 2) {
        q  = (const float*)small_p[0];
        k  = (const float*)small_p[1];
        v  = (const float*)small_p[2];
        dm = (const int*)big_p[0];
        bm = (const uint8_t*)big_p[1];
    } else {  // fallback: positional (dict order)
        q  = (const float*)d_in[0];
        k  = (const float*)d_in[1];
        v  = (const float*)d_in[2];
        dm = (const int*)d_in[3];
        bm = (const uint8_t*)d_in[4];
    }

    float* out  = (float*)d_out;                      // [B, L, D] first
    float* attn = out + (size_t)NB * L * D;           // then [B, L, L]

    dim3 grid(L / BM, NB);
    attn_fused<<<grid, 128>>>(q, k, v, dm, bm, out, attn);
}

// round 7
// speedup vs baseline: 1.5965x; 1.3784x over previous
#include <cuda_runtime.h>
#include <cuda_bf16.h>
#include <cstdint>

#define NB 32
#define L  2048
#define D  64
#define BM 64
#define BN 64

__device__ __forceinline__ uint32_t pack2(__nv_bfloat16 a, __nv_bfloat16 b) {
    return (uint32_t)__bfloat16_as_ushort(a) | ((uint32_t)__bfloat16_as_ushort(b) << 16);
}

// split fp32 pair into bf16 hi pair + bf16 lo (residual) pair
__device__ __forceinline__ void split2(float x, float y, uint32_t& hi, uint32_t& lo) {
    __nv_bfloat16 hx = __float2bfloat16(x);
    __nv_bfloat16 hy = __float2bfloat16(y);
    float rx = x - __bfloat162float(hx);
    float ry = y - __bfloat162float(hy);
    hi = pack2(hx, hy);
    lo = pack2(__float2bfloat16(rx), __float2bfloat16(ry));
}

// convert float4 -> 4 bf16 hi (uint2) + 4 bf16 lo (uint2)
__device__ __forceinline__ void cvt4(float4 f, uint2& hi, uint2& lo) {
    split2(f.x, f.y, hi.x, lo.x);
    split2(f.z, f.w, hi.y, lo.y);
}

__device__ __forceinline__ void mma_bf16(float c[4], const uint32_t a[4], uint32_t b0, uint32_t b1) {
    asm volatile(
        "mma.sync.aligned.m16n8k16.row.col.f32.bf16.bf16.f32 "
        "{%0,%1,%2,%3}, {%4,%5,%6,%7}, {%8,%9}, {%0,%1,%2,%3};\n"
        : "+f"(c[0]), "+f"(c[1]), "+f"(c[2]), "+f"(c[3])
        : "r"(a[0]), "r"(a[1]), "r"(a[2]), "r"(a[3]), "r"(b0), "r"(b1));
}

__device__ __forceinline__ void ldsm4(uint32_t& r0, uint32_t& r1, uint32_t& r2, uint32_t& r3,
                                      uint32_t addr) {
    asm volatile("ldmatrix.sync.aligned.m8n8.x4.shared.b16 {%0,%1,%2,%3}, [%4];\n"
                 : "=r"(r0), "=r"(r1), "=r"(r2), "=r"(r3) : "r"(addr));
}
__device__ __forceinline__ void ldsm4t(uint32_t& r0, uint32_t& r1, uint32_t& r2, uint32_t& r3,
                                       uint32_t addr) {
    asm volatile("ldmatrix.sync.aligned.m8n8.x4.trans.shared.b16 {%0,%1,%2,%3}, [%4];\n"
                 : "=r"(r0), "=r"(r1), "=r"(r2), "=r"(r3) : "r"(addr));
}

__global__ void __launch_bounds__(128, 3)
attn_fused(const float* __restrict__ q, const float* __restrict__ k,
           const float* __restrict__ v, const int* __restrict__ dmask,
           const uint8_t* __restrict__ bmask,
           float* __restrict__ out, float* __restrict__ attn)
{
    // padded to 72 elems/row (144B) -> conflict-free ldmatrix row addressing
    __shared__ __nv_bfloat16 sKhi[BN][72];
    __shared__ __nv_bfloat16 sKlo[BN][72];
    __shared__ __nv_bfloat16 sVhi[BN][72];   // row-major [kv][d]; transposed by ldmatrix.trans
    __shared__ __nv_bfloat16 sVlo[BN][72];
    __shared__ float sMj[32][64];            // per-tile running max, later cf
    __shared__ float sStatM[64];
    __shared__ float sStatL[64];

    const int b    = blockIdx.y;
    const int q0   = blockIdx.x * BM;
    const int tid  = threadIdx.x;
    const int warp = tid >> 5;
    const int lane = tid & 31;
    const int g    = lane >> 2;
    const int quad = lane & 3;
    const int tq   = lane >> 3;             // ldmatrix: tile index within x4
    const int tl   = lane & 7;              // ldmatrix: row within tile
    const int rl0  = warp * 16 + g;         // local row for c0/c1
    const int rl1  = rl0 + 8;
    const int row0 = q0 + rl0;              // global q row
    const int row1 = q0 + rl1;

    const float*   kb    = k     + ((size_t)b * L) * D;
    const float*   vb    = v     + ((size_t)b * L) * D;
    const int*     dmb   = dmask + (size_t)b * L * L;
    const uint8_t* bmb_u = bmask + (size_t)b * L * L;
    const int*     bmb_i = reinterpret_cast<const int*>(bmask) + (size_t)b * L * L;
    float*         attnb = attn  + (size_t)b * L * L;

    // smem base addresses (shared state space) for ldmatrix
    const uint32_t kHiB = (uint32_t)__cvta_generic_to_shared(&sKhi[0][0]);
    const uint32_t kLoB = (uint32_t)__cvta_generic_to_shared(&sKlo[0][0]);
    const uint32_t vHiB = (uint32_t)__cvta_generic_to_shared(&sVhi[0][0]);
    const uint32_t vLoB = (uint32_t)__cvta_generic_to_shared(&sVlo[0][0]);

    // ---- inline mask-dtype probe: int32 {0,1} has zero bytes at offset%4!=0 ----
    int nzp = 0;
    {
        const uint4* p4 = reinterpret_cast<const uint4*>(bmb_u);
        uint4 w0 = p4[tid];
        uint4 w1 = p4[128 + tid];
        nzp = (int)((w0.x | w0.y | w0.z | w0.w | w1.x | w1.y | w1.z | w1.w) & 0xFFFFFF00u);
    }
    const bool mi32 = (__syncthreads_or(nzp) == 0);

    // ---- load Q A-fragments once (hi/lo split), temperature folded in (x2^-3 exact) ----
    uint32_t aQh[16], aQl[16];
    {
        const float* qb = q + ((size_t)b * L) * D;
        #pragma unroll
        for (int ks = 0; ks < 4; ks++) {
            int c0 = ks * 16 + quad * 2;
            float2 x0 = *reinterpret_cast<const float2*>(qb + (size_t)row0 * D + c0);
            float2 x1 = *reinterpret_cast<const float2*>(qb + (size_t)row1 * D + c0);
            float2 x2 = *reinterpret_cast<const float2*>(qb + (size_t)row0 * D + c0 + 8);
            float2 x3 = *reinterpret_cast<const float2*>(qb + (size_t)row1 * D + c0 + 8);
            split2(x0.x * 0.125f, x0.y * 0.125f, aQh[ks*4+0], aQl[ks*4+0]);
            split2(x1.x * 0.125f, x1.y * 0.125f, aQh[ks*4+1], aQl[ks*4+1]);
            split2(x2.x * 0.125f, x2.y * 0.125f, aQh[ks*4+2], aQl[ks*4+2]);
            split2(x3.x * 0.125f, x3.y * 0.125f, aQh[ks*4+3], aQl[ks*4+3]);
        }
    }

    float oAcc[8][4];
    #pragma unroll
    for (int i = 0; i < 8; i++)
        oAcc[i][0] = oAcc[i][1] = oAcc[i][2] = oAcc[i][3] = 0.f;
    float mrun0 = -INFINITY, mrun1 = -INFINITY;
    float lrun0 = 0.f, lrun1 = 0.f;

    for (int j = 0; j < L / BN; j++) {
        // ---- stage K and V row-major as split bf16 (vectorized 8B stores) ----
        {
            const float* kt = kb + (size_t)j * BN * D;
            const float* vt = vb + (size_t)j * BN * D;
            #pragma unroll
            for (int t = 0; t < 8; t++) {
                int idx = t * 128 + tid;        // float4 index, 1024 total
                int r = idx >> 4;
                int c = (idx & 15) << 2;
                float4 k4 = *reinterpret_cast<const float4*>(kt + (size_t)r * D + c);
                float4 v4 = *reinterpret_cast<const float4*>(vt + (size_t)r * D + c);
                uint2 h, lo;
                cvt4(k4, h, lo);
                *reinterpret_cast<uint2*>(&sKhi[r][c]) = h;
                *reinterpret_cast<uint2*>(&sKlo[r][c]) = lo;
                cvt4(v4, h, lo);
                *reinterpret_cast<uint2*>(&sVhi[r][c]) = h;
                *reinterpret_cast<uint2*>(&sVlo[r][c]) = lo;
            }
        }
        __syncthreads();

        // ---- S = Q K^T (split bf16: hi*hi + hi*lo + lo*hi) ----
        float sAcc[8][4];
        #pragma unroll
        for (int nt = 0; nt < 8; nt++)
            sAcc[nt][0] = sAcc[nt][1] = sAcc[nt][2] = sAcc[nt][3] = 0.f;

        #pragma unroll
        for (int nt = 0; nt < 8; nt++) {
            // ldmatrix non-trans: tile t covers K[nt*8 .. +7][p*32 + t*8 .. +7]
            uint32_t rowOff = (uint32_t)(nt * 8 + tl) * 144u;
            #pragma unroll
            for (int p = 0; p < 2; p++) {       // ksPair: ks = 2p, 2p+1
                uint32_t off = rowOff + (uint32_t)(p * 32 + tq * 8) * 2u;
                uint32_t bh0, bh1, bh2, bh3, bl0, bl1, bl2, bl3;
                ldsm4 (bh0, bh1, bh2, bh3, kHiB + off);
                ldsm4 (bl0, bl1, bl2, bl3, kLoB + off);
                mma_bf16(sAcc[nt], &aQh[(2*p  )*4], bh0, bh1);
                mma_bf16(sAcc[nt], &aQh[(2*p  )*4], bl0, bl1);
                mma_bf16(sAcc[nt], &aQl[(2*p  )*4], bh0, bh1);
                mma_bf16(sAcc[nt], &aQh[(2*p+1)*4], bh2, bh3);
                mma_bf16(sAcc[nt], &aQh[(2*p+1)*4], bl2, bl3);
                mma_bf16(sAcc[nt], &aQl[(2*p+1)*4], bh2, bh3);
            }
        }

        // ---- masks, tile row-max ----
        float tmax0 = -INFINITY, tmax1 = -INFINITY;
        #pragma unroll
        for (int nt = 0; nt < 8; nt++) {
            int col = j * BN + nt * 8 + quad * 2;
            int2 d0v = *reinterpret_cast<const int2*>(dmb + (size_t)row0 * L + col);
            int2 d1v = *reinterpret_cast<const int2*>(dmb + (size_t)row1 * L + col);
            bool mk0x, mk0y, mk1x, mk1y;
            if (mi32) {
                int2 a0 = *reinterpret_cast<const int2*>(bmb_i + (size_t)row0 * L + col);
                int2 a1 = *reinterpret_cast<const int2*>(bmb_i + (size_t)row1 * L + col);
                mk0x = (a0.x != 0); mk0y = (a0.y != 0);
                mk1x = (a1.x != 0); mk1y = (a1.y != 0);
            } else {
                uchar2 a0 = *reinterpret_cast<const uchar2*>(bmb_u + (size_t)row0 * L + col);
                uchar2 a1 = *reinterpret_cast<const uchar2*>(bmb_u + (size_t)row1 * L + col);
                mk0x = (a0.x != 0); mk0y = (a0.y != 0);
                mk1x = (a1.x != 0); mk1y = (a1.y != 0);
            }
            float s0 = sAcc[nt][0];
            float s1 = sAcc[nt][1];
            float s2 = sAcc[nt][2];
            float s3 = sAcc[nt][3];
            if (mk0x)       s0 = -INFINITY;
            if (d0v.x == 0) s0 = -1e32f;
            if (mk0y)       s1 = -INFINITY;
            if (d0v.y == 0) s1 = -1e32f;
            if (mk1x)       s2 = -INFINITY;
            if (d1v.x == 0) s2 = -1e32f;
            if (mk1y)       s3 = -INFINITY;
            if (d1v.y == 0) s3 = -1e32f;
            sAcc[nt][0] = s0; sAcc[nt][1] = s1; sAcc[nt][2] = s2; sAcc[nt][3] = s3;
            tmax0 = fmaxf(tmax0, fmaxf(s0, s1));
            tmax1 = fmaxf(tmax1, fmaxf(s2, s3));
        }
        tmax0 = fmaxf(tmax0, __shfl_xor_sync(0xffffffffu, tmax0, 1));
        tmax0 = fmaxf(tmax0, __shfl_xor_sync(0xffffffffu, tmax0, 2));
        tmax1 = fmaxf(tmax1, __shfl_xor_sync(0xffffffffu, tmax1, 1));
        tmax1 = fmaxf(tmax1, __shfl_xor_sync(0xffffffffu, tmax1, 2));

        float mnew0 = fmaxf(mrun0, tmax0);
        float mnew1 = fmaxf(mrun1, tmax1);
        float alpha0 = (mnew0 == -INFINITY) ? 1.0f : __expf(mrun0 - mnew0);
        float alpha1 = (mnew1 == -INFINITY) ? 1.0f : __expf(mrun1 - mnew1);
        mrun0 = mnew0; mrun1 = mnew1;

        if (quad == 0) {
            sMj[j][rl0] = mnew0;
            sMj[j][rl1] = mnew1;
        }

        // ---- p = exp(s - m_j): store p to attn (corrected in epilogue), row sums ----
        float rs0 = 0.f, rs1 = 0.f;
        #pragma unroll
        for (int nt = 0; nt < 8; nt++) {
            float p0 = __expf(sAcc[nt][0] - mnew0);   // -inf/-1e32 underflow to exact 0
            float p1 = __expf(sAcc[nt][1] - mnew0);
            float p2 = __expf(sAcc[nt][2] - mnew1);
            float p3 = __expf(sAcc[nt][3] - mnew1);
            int col = j * BN + nt * 8 + quad * 2;
            *reinterpret_cast<float2*>(attnb + (size_t)row0 * L + col) = make_float2(p0, p1);
            *reinterpret_cast<float2*>(attnb + (size_t)row1 * L + col) = make_float2(p2, p3);
            sAcc[nt][0] = p0; sAcc[nt][1] = p1; sAcc[nt][2] = p2; sAcc[nt][3] = p3;
            rs0 += p0 + p1;
            rs1 += p2 + p3;
        }
        rs0 += __shfl_xor_sync(0xffffffffu, rs0, 1);
        rs0 += __shfl_xor_sync(0xffffffffu, rs0, 2);
        rs1 += __shfl_xor_sync(0xffffffffu, rs1, 1);
        rs1 += __shfl_xor_sync(0xffffffffu, rs1, 2);
        lrun0 = lrun0 * alpha0 + rs0;
        lrun1 = lrun1 * alpha1 + rs1;

        // ---- O = O*alpha + P @ V (split bf16, V via ldmatrix.trans) ----
        #pragma unroll
        for (int dt = 0; dt < 8; dt++) {
            oAcc[dt][0] *= alpha0; oAcc[dt][1] *= alpha0;
            oAcc[dt][2] *= alpha1; oAcc[dt][3] *= alpha1;
        }
        #pragma unroll
        for (int kn = 0; kn < 4; kn++) {
            // S C-fragment layout == P A-fragment layout
            uint32_t pah[4], pal[4];
            split2(sAcc[2*kn  ][0], sAcc[2*kn  ][1], pah[0], pal[0]);
            split2(sAcc[2*kn  ][2], sAcc[2*kn  ][3], pah[1], pal[1]);
            split2(sAcc[2*kn+1][0], sAcc[2*kn+1][1], pah[2], pal[2]);
            split2(sAcc[2*kn+1][2], sAcc[2*kn+1][3], pah[3], pal[3]);
            // ldmatrix.trans tiles: t0=(kn*16, d), t1=(kn*16+8, d), t2=(kn*16, d+8), t3=(kn*16+8, d+8)
            uint32_t rowOff = (uint32_t)(kn * 16 + (tq & 1) * 8 + tl) * 144u;
            #pragma unroll
            for (int dtp = 0; dtp < 4; dtp++) {   // dt = 2*dtp, 2*dtp+1
                uint32_t off = rowOff + (uint32_t)(dtp * 16 + (tq >> 1) * 8) * 2u;
                uint32_t bh0, bh1, bh2, bh3, bl0, bl1, bl2, bl3;
                ldsm4t(bh0, bh1, bh2, bh3, vHiB + off);
                ldsm4t(bl0, bl1, bl2, bl3, vLoB + off);
                mma_bf16(oAcc[2*dtp  ], pah, bh0, bh1);
                mma_bf16(oAcc[2*dtp  ], pah, bl0, bl1);
                mma_bf16(oAcc[2*dtp  ], pal, bh0, bh1);
                mma_bf16(oAcc[2*dtp+1], pah, bh2, bh3);
                mma_bf16(oAcc[2*dtp+1], pah, bl2, bl3);
                mma_bf16(oAcc[2*dtp+1], pal, bh2, bh3);
            }
        }
        __syncthreads();
    }

    // ---- O epilogue: O / l ----
    float rlv0 = 1.0f / lrun0;
    float rlv1 = 1.0f / lrun1;
    float* ob = out + ((size_t)b * L) * D;
    #pragma unroll
    for (int dt = 0; dt < 8; dt++) {
        int dc = dt * 8 + quad * 2;
        *reinterpret_cast<float2*>(ob + (size_t)row0 * D + dc) =
            make_float2(oAcc[dt][0] * rlv0, oAcc[dt][1] * rlv0);
        *reinterpret_cast<float2*>(ob + (size_t)row1 * D + dc) =
            make_float2(oAcc[dt][2] * rlv1, oAcc[dt][3] * rlv1);
    }

    // ---- attn epilogue: per-(row,tile) correction cf = exp(m_j - m_fin) / l ----
    if (quad == 0) {
        sStatM[rl0] = mrun0; sStatM[rl1] = mrun1;
        sStatL[rl0] = rlv0;  sStatL[rl1] = rlv1;
    }
    __syncthreads();
    #pragma unroll
    for (int i = tid; i < 32 * 64; i += 128) {
        int t = i >> 6, r = i & 63;
        sMj[t][r] = __expf(sMj[t][r] - sStatM[r]) * sStatL[r];
    }
    __syncthreads();

    // stream 64 rows x 512 float4: p *= cf
    float4* a4 = reinterpret_cast<float4*>(attnb + (size_t)q0 * L);
    #pragma unroll 4
    for (int i = tid; i < 64 * 512; i += 128) {
        int r  = i >> 9;
        int c4 = i & 511;
        float cf = sMj[c4 >> 4][r];
        float4 sv = a4[i];
        sv.x *= cf; sv.y *= cf; sv.z *= cf; sv.w *= cf;
        a4[i] = sv;
    }
}

extern "C" void kernel_launch(void* const* d_in, const int* in_sizes, int n_in,
                              void* d_out, int out_size)
{
    // Robust binding by element count: q,k,v = NB*L*D; diag_mask, mask = NB*L*L.
    const int SMALL = NB * L * D;       // 4194304
    const void* small_p[3] = {nullptr, nullptr, nullptr};
    const void* big_p[2]   = {nullptr, nullptr};
    int ns = 0, nb = 0;
    for (int i = 0; i < n_in; i++) {
        if (in_sizes[i] == SMALL) { if (ns < 3) small_p[ns++] = d_in[i]; }
        else                      { if (nb < 2) big_p[nb++]   = d_in[i]; }
    }
    const float*   q, *k, *v;
    const int*     dm;
    const uint8_t* bm;
    if (ns == 3 && nb == 2) {
        q  = (const float*)small_p[0];
        k  = (const float*)small_p[1];
        v  = (const float*)small_p[2];
        dm = (const int*)big_p[0];
        bm = (const uint8_t*)big_p[1];
    } else {  // fallback: positional (dict order)
        q  = (const float*)d_in[0];
        k  = (const float*)d_in[1];
        v  = (const float*)d_in[2];
        dm = (const int*)d_in[3];
        bm = (const uint8_t*)d_in[4];
    }

    float* out  = (float*)d_out;                      // [B, L, D] first
    float* attn = out + (size_t)NB * L * D;           // then [B, L, L]

    dim3 grid(L / BM, NB);
    attn_fused<<<grid, 128>>>(q, k, v, dm, bm, out, attn);
}

// round 8
// speedup vs baseline: 1.8145x; 1.1365x over previous
#include <cuda_runtime.h>
#include <cuda_bf16.h>
#include <cstdint>

#define NB 32
#define L  2048
#define D  64
#define BM 64
#define BN 64

// pre-split K/V scratch (bf16 hi/lo), 8.4 MB each
__device__ __align__(16) __nv_bfloat16 g_khi[NB * L * D];
__device__ __align__(16) __nv_bfloat16 g_klo[NB * L * D];
__device__ __align__(16) __nv_bfloat16 g_vhi[NB * L * D];
__device__ __align__(16) __nv_bfloat16 g_vlo[NB * L * D];

// dynamic smem layout (bytes):
//   K:  [0,36864)   buf0 hi [0,9216) | buf0 lo [9216,18432) | buf1 hi [18432,27648) | buf1 lo [27648,36864)
//   V:  hi [36864,46080) | lo [46080,55296)
//   sMj [55296,63488)  statM [63488,63744)  statL [63744,64000)
#define SM_KBUF_STRIDE 18432
#define SM_KLO_OFF     9216
#define SM_VHI_OFF     36864
#define SM_VLO_OFF     46080
#define SM_MJ_OFF      55296
#define SM_STATM_OFF   63488
#define SM_STATL_OFF   63744
#define SMEM_BYTES     64000

__device__ __forceinline__ uint32_t pack2(__nv_bfloat16 a, __nv_bfloat16 b) {
    return (uint32_t)__bfloat16_as_ushort(a) | ((uint32_t)__bfloat16_as_ushort(b) << 16);
}

__device__ __forceinline__ void split2(float x, float y, uint32_t& hi, uint32_t& lo) {
    __nv_bfloat16 hx = __float2bfloat16(x);
    __nv_bfloat16 hy = __float2bfloat16(y);
    float rx = x - __bfloat162float(hx);
    float ry = y - __bfloat162float(hy);
    hi = pack2(hx, hy);
    lo = pack2(__float2bfloat16(rx), __float2bfloat16(ry));
}

__device__ __forceinline__ void cvt4(float4 f, uint2& hi, uint2& lo) {
    split2(f.x, f.y, hi.x, lo.x);
    split2(f.z, f.w, hi.y, lo.y);
}

__device__ __forceinline__ void mma_bf16(float c[4], const uint32_t a[4], uint32_t b0, uint32_t b1) {
    asm volatile(
        "mma.sync.aligned.m16n8k16.row.col.f32.bf16.bf16.f32 "
        "{%0,%1,%2,%3}, {%4,%5,%6,%7}, {%8,%9}, {%0,%1,%2,%3};\n"
        : "+f"(c[0]), "+f"(c[1]), "+f"(c[2]), "+f"(c[3])
        : "r"(a[0]), "r"(a[1]), "r"(a[2]), "r"(a[3]), "r"(b0), "r"(b1));
}

__device__ __forceinline__ void ldsm4(uint32_t& r0, uint32_t& r1, uint32_t& r2, uint32_t& r3,
                                      uint32_t addr) {
    asm volatile("ldmatrix.sync.aligned.m8n8.x4.shared.b16 {%0,%1,%2,%3}, [%4];\n"
                 : "=r"(r0), "=r"(r1), "=r"(r2), "=r"(r3) : "r"(addr));
}
__device__ __forceinline__ void ldsm4t(uint32_t& r0, uint32_t& r1, uint32_t& r2, uint32_t& r3,
                                       uint32_t addr) {
    asm volatile("ldmatrix.sync.aligned.m8n8.x4.trans.shared.b16 {%0,%1,%2,%3}, [%4];\n"
                 : "=r"(r0), "=r"(r1), "=r"(r2), "=r"(r3) : "r"(addr));
}

__device__ __forceinline__ void cpasync16(uint32_t dst, const void* src) {
    asm volatile("cp.async.cg.shared.global [%0], [%1], 16;\n" :: "r"(dst), "l"(src));
}
#define CP_COMMIT() asm volatile("cp.async.commit_group;\n" ::: "memory")
#define CP_WAIT(n)  asm volatile("cp.async.wait_group %0;\n" :: "n"(n) : "memory")

// one-time fp32 -> split bf16 conversion of K and V
__global__ void __launch_bounds__(256)
presplit(const float* __restrict__ k, const float* __restrict__ v) {
    unsigned i = blockIdx.x * 256u + threadIdx.x;   // float4 index, total NB*L*D/4
    float4 k4 = reinterpret_cast<const float4*>(k)[i];
    float4 v4 = reinterpret_cast<const float4*>(v)[i];
    uint2 h, lo;
    cvt4(k4, h, lo);
    reinterpret_cast<uint2*>(g_khi)[i] = h;
    reinterpret_cast<uint2*>(g_klo)[i] = lo;
    cvt4(v4, h, lo);
    reinterpret_cast<uint2*>(g_vhi)[i] = h;
    reinterpret_cast<uint2*>(g_vlo)[i] = lo;
}

__global__ void __launch_bounds__(128, 3)
attn_fused(const float* __restrict__ q, const int* __restrict__ dmask,
           const uint8_t* __restrict__ bmask,
           float* __restrict__ out, float* __restrict__ attn)
{
    extern __shared__ char smem_raw[];
    const uint32_t smB = (uint32_t)__cvta_generic_to_shared(smem_raw);
    float* sMj    = reinterpret_cast<float*>(smem_raw + SM_MJ_OFF);     // [32][64]
    float* sStatM = reinterpret_cast<float*>(smem_raw + SM_STATM_OFF);  // [64]
    float* sStatL = reinterpret_cast<float*>(smem_raw + SM_STATL_OFF);  // [64]

    const int b    = blockIdx.y;
    const int q0   = blockIdx.x * BM;
    const int tid  = threadIdx.x;
    const int warp = tid >> 5;
    const int lane = tid & 31;
    const int g    = lane >> 2;
    const int quad = lane & 3;
    const int tq   = lane >> 3;             // ldmatrix tile index within x4
    const int tl   = lane & 7;              // ldmatrix row within tile
    const int rl0  = warp * 16 + g;
    const int rl1  = rl0 + 8;
    const int row0 = q0 + rl0;
    const int row1 = q0 + rl1;

    // staging index decomposition (shared by K and V stagers)
    const int s_r  = tid >> 3;              // smem row handled (pass adds +?); tid..: c = tid + i*128
    const int s_c  = (tid & 7) << 3;        // col start (8 bf16 = 16B)

    const size_t  kvBase = ((size_t)b * L) * D;
    const int*     dmb   = dmask + (size_t)b * L * L;
    const uint8_t* bmb_u = bmask + (size_t)b * L * L;
    const int*     bmb_i = reinterpret_cast<const int*>(bmask) + (size_t)b * L * L;
    float*         attnb = attn  + (size_t)b * L * L;

    // ---- prologue: start K0 and V0 staging immediately ----
    {
        const __nv_bfloat16* sh = g_khi + kvBase;
        const __nv_bfloat16* sl = g_klo + kvBase;
        #pragma unroll
        for (int i = 0; i < 4; i++) {
            int rr = s_r + i * 16;
            cpasync16(smB + rr * 144 + s_c * 2,             sh + rr * 64 + s_c);
            cpasync16(smB + SM_KLO_OFF + rr * 144 + s_c * 2, sl + rr * 64 + s_c);
        }
        CP_COMMIT();
        const __nv_bfloat16* vh = g_vhi + kvBase;
        const __nv_bfloat16* vl = g_vlo + kvBase;
        #pragma unroll
        for (int i = 0; i < 4; i++) {
            int rr = s_r + i * 16;
            cpasync16(smB + SM_VHI_OFF + rr * 144 + s_c * 2, vh + rr * 64 + s_c);
            cpasync16(smB + SM_VLO_OFF + rr * 144 + s_c * 2, vl + rr * 64 + s_c);
        }
        CP_COMMIT();
    }

    // ---- mask-dtype probe (overlaps staging latency) ----
    int nzp = 0;
    {
        const uint4* p4 = reinterpret_cast<const uint4*>(bmb_u);
        uint4 w0 = p4[tid];
        uint4 w1 = p4[128 + tid];
        nzp = (int)((w0.x | w0.y | w0.z | w0.w | w1.x | w1.y | w1.z | w1.w) & 0xFFFFFF00u);
    }
    const bool mi32 = (__syncthreads_or(nzp) == 0);

    // ---- Q A-fragments (hi/lo split), temperature folded in (x2^-3 exact) ----
    uint32_t aQh[16], aQl[16];
    {
        const float* qb = q + kvBase;
        #pragma unroll
        for (int ks = 0; ks < 4; ks++) {
            int c0 = ks * 16 + quad * 2;
            float2 x0 = *reinterpret_cast<const float2*>(qb + (size_t)row0 * D + c0);
            float2 x1 = *reinterpret_cast<const float2*>(qb + (size_t)row1 * D + c0);
            float2 x2 = *reinterpret_cast<const float2*>(qb + (size_t)row0 * D + c0 + 8);
            float2 x3 = *reinterpret_cast<const float2*>(qb + (size_t)row1 * D + c0 + 8);
            split2(x0.x * 0.125f, x0.y * 0.125f, aQh[ks*4+0], aQl[ks*4+0]);
            split2(x1.x * 0.125f, x1.y * 0.125f, aQh[ks*4+1], aQl[ks*4+1]);
            split2(x2.x * 0.125f, x2.y * 0.125f, aQh[ks*4+2], aQl[ks*4+2]);
            split2(x3.x * 0.125f, x3.y * 0.125f, aQh[ks*4+3], aQl[ks*4+3]);
        }
    }

    float oAcc[8][4];
    #pragma unroll
    for (int i = 0; i < 8; i++)
        oAcc[i][0] = oAcc[i][1] = oAcc[i][2] = oAcc[i][3] = 0.f;
    float mrun0 = -INFINITY, mrun1 = -INFINITY;
    float lrun0 = 0.f, lrun1 = 0.f;

    for (int j = 0; j < L / BN; j++) {
        const int buf = j & 1;
        const uint32_t kHiB = smB + buf * SM_KBUF_STRIDE;
        const uint32_t kLoB = kHiB + SM_KLO_OFF;

        CP_WAIT(1);              // K[j] resident (V[j] may still fly)
        __syncthreads();

        // ---- S = Q K^T (split bf16: hi*hi + hi*lo + lo*hi) ----
        float sAcc[8][4];
        #pragma unroll
        for (int nt = 0; nt < 8; nt++)
            sAcc[nt][0] = sAcc[nt][1] = sAcc[nt][2] = sAcc[nt][3] = 0.f;

        #pragma unroll
        for (int nt = 0; nt < 8; nt++) {
            uint32_t rowOff = (uint32_t)(nt * 8 + tl) * 144u;
            #pragma unroll
            for (int p = 0; p < 2; p++) {
                uint32_t off = rowOff + (uint32_t)(p * 32 + tq * 8) * 2u;
                uint32_t bh0, bh1, bh2, bh3, bl0, bl1, bl2, bl3;
                ldsm4(bh0, bh1, bh2, bh3, kHiB + off);
                ldsm4(bl0, bl1, bl2, bl3, kLoB + off);
                mma_bf16(sAcc[nt], &aQh[(2*p  )*4], bh0, bh1);
                mma_bf16(sAcc[nt], &aQh[(2*p  )*4], bl0, bl1);
                mma_bf16(sAcc[nt], &aQl[(2*p  )*4], bh0, bh1);
                mma_bf16(sAcc[nt], &aQh[(2*p+1)*4], bh2, bh3);
                mma_bf16(sAcc[nt], &aQh[(2*p+1)*4], bl2, bl3);
                mma_bf16(sAcc[nt], &aQl[(2*p+1)*4], bh2, bh3);
            }
        }

        // ---- prefetch K[j+1] into the other K buffer (overlaps rest of tile) ----
        if (j + 1 < L / BN) {
            const size_t tb = kvBase + (size_t)(j + 1) * BN * D;
            const __nv_bfloat16* sh = g_khi + tb;
            const __nv_bfloat16* sl = g_klo + tb;
            const uint32_t dstB = smB + (buf ^ 1) * SM_KBUF_STRIDE;
            #pragma unroll
            for (int i = 0; i < 4; i++) {
                int rr = s_r + i * 16;
                cpasync16(dstB + rr * 144 + s_c * 2,              sh + rr * 64 + s_c);
                cpasync16(dstB + SM_KLO_OFF + rr * 144 + s_c * 2, sl + rr * 64 + s_c);
            }
            CP_COMMIT();
        }

        // ---- masks, tile row-max ----
        float tmax0 = -INFINITY, tmax1 = -INFINITY;
        #pragma unroll
        for (int nt = 0; nt < 8; nt++) {
            int col = j * BN + nt * 8 + quad * 2;
            int2 d0v = *reinterpret_cast<const int2*>(dmb + (size_t)row0 * L + col);
            int2 d1v = *reinterpret_cast<const int2*>(dmb + (size_t)row1 * L + col);
            bool mk0x, mk0y, mk1x, mk1y;
            if (mi32) {
                int2 a0 = *reinterpret_cast<const int2*>(bmb_i + (size_t)row0 * L + col);
                int2 a1 = *reinterpret_cast<const int2*>(bmb_i + (size_t)row1 * L + col);
                mk0x = (a0.x != 0); mk0y = (a0.y != 0);
                mk1x = (a1.x != 0); mk1y = (a1.y != 0);
            } else {
                uchar2 a0 = *reinterpret_cast<const uchar2*>(bmb_u + (size_t)row0 * L + col);
                uchar2 a1 = *reinterpret_cast<const uchar2*>(bmb_u + (size_t)row1 * L + col);
                mk0x = (a0.x != 0); mk0y = (a0.y != 0);
                mk1x = (a1.x != 0); mk1y = (a1.y != 0);
            }
            float s0 = sAcc[nt][0];
            float s1 = sAcc[nt][1];
            float s2 = sAcc[nt][2];
            float s3 = sAcc[nt][3];
            if (mk0x)       s0 = -INFINITY;
            if (d0v.x == 0) s0 = -1e32f;
            if (mk0y)       s1 = -INFINITY;
            if (d0v.y == 0) s1 = -1e32f;
            if (mk1x)       s2 = -INFINITY;
            if (d1v.x == 0) s2 = -1e32f;
            if (mk1y)       s3 = -INFINITY;
            if (d1v.y == 0) s3 = -1e32f;
            sAcc[nt][0] = s0; sAcc[nt][1] = s1; sAcc[nt][2] = s2; sAcc[nt][3] = s3;
            tmax0 = fmaxf(tmax0, fmaxf(s0, s1));
            tmax1 = fmaxf(tmax1, fmaxf(s2, s3));
        }
        tmax0 = fmaxf(tmax0, __shfl_xor_sync(0xffffffffu, tmax0, 1));
        tmax0 = fmaxf(tmax0, __shfl_xor_sync(0xffffffffu, tmax0, 2));
        tmax1 = fmaxf(tmax1, __shfl_xor_sync(0xffffffffu, tmax1, 1));
        tmax1 = fmaxf(tmax1, __shfl_xor_sync(0xffffffffu, tmax1, 2));

        float mnew0 = fmaxf(mrun0, tmax0);
        float mnew1 = fmaxf(mrun1, tmax1);
        float alpha0 = (mnew0 == -INFINITY) ? 1.0f : __expf(mrun0 - mnew0);
        float alpha1 = (mnew1 == -INFINITY) ? 1.0f : __expf(mrun1 - mnew1);
        mrun0 = mnew0; mrun1 = mnew1;

        if (quad == 0) {
            sMj[j * 64 + rl0] = mnew0;
            sMj[j * 64 + rl1] = mnew1;
        }

        // ---- p = exp(s - m_j): store to attn (corrected in epilogue), row sums ----
        float rs0 = 0.f, rs1 = 0.f;
        #pragma unroll
        for (int nt = 0; nt < 8; nt++) {
            float p0 = __expf(sAcc[nt][0] - mnew0);   // -inf/-1e32 underflow to exact 0
            float p1 = __expf(sAcc[nt][1] - mnew0);
            float p2 = __expf(sAcc[nt][2] - mnew1);
            float p3 = __expf(sAcc[nt][3] - mnew1);
            int col = j * BN + nt * 8 + quad * 2;
            *reinterpret_cast<float2*>(attnb + (size_t)row0 * L + col) = make_float2(p0, p1);
            *reinterpret_cast<float2*>(attnb + (size_t)row1 * L + col) = make_float2(p2, p3);
            sAcc[nt][0] = p0; sAcc[nt][1] = p1; sAcc[nt][2] = p2; sAcc[nt][3] = p3;
            rs0 += p0 + p1;
            rs1 += p2 + p3;
        }
        rs0 += __shfl_xor_sync(0xffffffffu, rs0, 1);
        rs0 += __shfl_xor_sync(0xffffffffu, rs0, 2);
        rs1 += __shfl_xor_sync(0xffffffffu, rs1, 1);
        rs1 += __shfl_xor_sync(0xffffffffu, rs1, 2);
        lrun0 = lrun0 * alpha0 + rs0;
        lrun1 = lrun1 * alpha1 + rs1;

        // ---- wait V[j], then PV ----
        if (j + 1 < L / BN) { CP_WAIT(1); } else { CP_WAIT(0); }
        __syncthreads();

        #pragma unroll
        for (int dt = 0; dt < 8; dt++) {
            oAcc[dt][0] *= alpha0; oAcc[dt][1] *= alpha0;
            oAcc[dt][2] *= alpha1; oAcc[dt][3] *= alpha1;
        }
        const uint32_t vHiB = smB + SM_VHI_OFF;
        const uint32_t vLoB = smB + SM_VLO_OFF;
        #pragma unroll
        for (int kn = 0; kn < 4; kn++) {
            uint32_t pah[4], pal[4];
            split2(sAcc[2*kn  ][0], sAcc[2*kn  ][1], pah[0], pal[0]);
            split2(sAcc[2*kn  ][2], sAcc[2*kn  ][3], pah[1], pal[1]);
            split2(sAcc[2*kn+1][0], sAcc[2*kn+1][1], pah[2], pal[2]);
            split2(sAcc[2*kn+1][2], sAcc[2*kn+1][3], pah[3], pal[3]);
            uint32_t rowOff = (uint32_t)(kn * 16 + (tq & 1) * 8 + tl) * 144u;
            #pragma unroll
            for (int dtp = 0; dtp < 4; dtp++) {
                uint32_t off = rowOff + (uint32_t)(dtp * 16 + (tq >> 1) * 8) * 2u;
                uint32_t bh0, bh1, bh2, bh3, bl0, bl1, bl2, bl3;
                ldsm4t(bh0, bh1, bh2, bh3, vHiB + off);
                ldsm4t(bl0, bl1, bl2, bl3, vLoB + off);
                mma_bf16(oAcc[2*dtp  ], pah, bh0, bh1);
                mma_bf16(oAcc[2*dtp  ], pah, bl0, bl1);
                mma_bf16(oAcc[2*dtp  ], pal, bh0, bh1);
                mma_bf16(oAcc[2*dtp+1], pah, bh2, bh3);
                mma_bf16(oAcc[2*dtp+1], pah, bl2, bl3);
                mma_bf16(oAcc[2*dtp+1], pal, bh2, bh3);
            }
        }
        __syncthreads();

        // ---- stage V[j+1] (single buffer, now free) ----
        if (j + 1 < L / BN) {
            const size_t tb = kvBase + (size_t)(j + 1) * BN * D;
            const __nv_bfloat16* vh = g_vhi + tb;
            const __nv_bfloat16* vl = g_vlo + tb;
            #pragma unroll
            for (int i = 0; i < 4; i++) {
                int rr = s_r + i * 16;
                cpasync16(smB + SM_VHI_OFF + rr * 144 + s_c * 2, vh + rr * 64 + s_c);
                cpasync16(smB + SM_VLO_OFF + rr * 144 + s_c * 2, vl + rr * 64 + s_c);
            }
            CP_COMMIT();
        }
    }

    // ---- O epilogue: O / l ----
    float rlv0 = 1.0f / lrun0;
    float rlv1 = 1.0f / lrun1;
    float* ob = out + ((size_t)b * L) * D;
    #pragma unroll
    for (int dt = 0; dt < 8; dt++) {
        int dc = dt * 8 + quad * 2;
        *reinterpret_cast<float2*>(ob + (size_t)row0 * D + dc) =
            make_float2(oAcc[dt][0] * rlv0, oAcc[dt][1] * rlv0);
        *reinterpret_cast<float2*>(ob + (size_t)row1 * D + dc) =
            make_float2(oAcc[dt][2] * rlv1, oAcc[dt][3] * rlv1);
    }

    // ---- attn epilogue: per-(row,tile) correction cf = exp(m_j - m_fin) / l ----
    if (quad == 0) {
        sStatM[rl0] = mrun0; sStatM[rl1] = mrun1;
        sStatL[rl0] = rlv0;  sStatL[rl1] = rlv1;
    }
    __syncthreads();
    #pragma unroll
    for (int i = tid; i < 32 * 64; i += 128) {
        int t = i >> 6, r = i & 63;
        sMj[t * 64 + r] = __expf(sMj[t * 64 + r] - sStatM[r]) * sStatL[r];
    }
    __syncthreads();

    float4* a4 = reinterpret_cast<float4*>(attnb + (size_t)q0 * L);
    #pragma unroll 4
    for (int i = tid; i < 64 * 512; i += 128) {
        int r  = i >> 9;
        int c4 = i & 511;
        float cf = sMj[(c4 >> 4) * 64 + r];
        float4 sv = a4[i];
        sv.x *= cf; sv.y *= cf; sv.z *= cf; sv.w *= cf;
        a4[i] = sv;
    }
}

extern "C" void kernel_launch(void* const* d_in, const int* in_sizes, int n_in,
                              void* d_out, int out_size)
{
    // Robust binding by element count: q,k,v = NB*L*D; diag_mask, mask = NB*L*L.
    const int SMALL = NB * L * D;
    const void* small_p[3] = {nullptr, nullptr, nullptr};
    const void* big_p[2]   = {nullptr, nullptr};
    int ns = 0, nb = 0;
    for (int i = 0; i < n_in; i++) {
        if (in_sizes[i] == SMALL) { if (ns < 3) small_p[ns++] = d_in[i]; }
        else                      { if (nb < 2) big_p[nb++]   = d_in[i]; }
    }
    const float*   q, *k, *v;
    const int*     dm;
    const uint8_t* bm;
    if (ns == 3 && nb == 2) {
        q  = (const float*)small_p[0];
        k  = (const float*)small_p[1];
        v  = (const float*)small_p[2];
        dm = (const int*)big_p[0];
        bm = (const uint8_t*)big_p[1];
    } else {
        q  = (const float*)d_in[0];
        k  = (const float*)d_in[1];
        v  = (const float*)d_in[2];
        dm = (const int*)d_in[3];
        bm = (const uint8_t*)d_in[4];
    }

    float* out  = (float*)d_out;                      // [B, L, D] first
    float* attn = out + (size_t)NB * L * D;           // then [B, L, L]

    cudaFuncSetAttribute(attn_fused, cudaFuncAttributeMaxDynamicSharedMemorySize, SMEM_BYTES);

    presplit<<<NB * L * D / 4 / 256, 256>>>(k, v);
    dim3 grid(L / BM, NB);
    attn_fused<<<grid, 128, SMEM_BYTES>>>(q, dm, bm, out, attn);
}